// round 2
// baseline (speedup 1.0000x reference)
#include <cuda_runtime.h>
#include <cstdint>
#include <cstddef>

#define T_STEPS 1024
#define BATCH   128
#define INDIM   100
#define HID     200
#define NCLS    100
#define NBG     4
#define MB      32
#define NHG     34
#define NHU     6
#define NG      24          // 4 gates * NHU
#define NTHR    128
#define NCTA    (NBG*NHG)   // 136
#define K0      300         // INDIM + HID
#define K1      400         // HID + HID
#define XSTR    36          // smem stride for [k][batch] staging buffer

#define HN_OFF  (T_STEPS*BATCH*NCLS)            // 13,107,200
#define CN_OFF  (HN_OFF + 2*BATCH*HID)          // 13,158,400

// smem layout (floats)
#define OFF_W0  0
#define OFF_W1  7200
#define OFF_XH  16800
#define OFF_GB  34800
#define OFF_B0  35568
#define OFF_B1  35592
#define OFF_C0  35616
#define OFF_C1  35808
#define SMEM_FLOATS 36000
#define SMEM_BYTES  (SMEM_FLOATS*4)

#define FC_SMEM_BYTES ((NCLS*HID + 128)*4)

// -------- device scratch (static allocation is allowed) --------
__device__ __align__(256) float g_ph0[2][HID*BATCH];
__device__ __align__(256) float g_ph1[2][HID*BATCH];
__device__ __align__(256) float g_y1[(size_t)T_STEPS*HID*BATCH];
__device__ volatile unsigned g_bar[NBG*32];   // one counter per batch group, padded

__global__ void bar_reset_kernel() {
    int i = threadIdx.x;
    if (i < NBG*32) g_bar[i] = 0u;
}

__device__ __forceinline__ float sigm(float x) {
    // accurate enough: MUFU ex2 + fast reciprocal, rel err ~1e-6
    return __fdividef(1.0f, 1.0f + __expf(-x));
}
__device__ __forceinline__ float tanha(float x) {
    return fmaf(2.0f, sigm(2.0f * x), -1.0f);
}

// monotonic group barrier among the NHG CTAs of one batch group
__device__ __forceinline__ void group_barrier(int bg, unsigned target) {
    __syncthreads();
    if (threadIdx.x == 0) {
        __threadfence();                         // release (cumulative)
        atomicAdd((unsigned*)&g_bar[bg*32], 1u);
        while (g_bar[bg*32] < target) { __nanosleep(64); }
        __threadfence();                         // acquire
    }
    __syncthreads();
}

// gates[row][b] = bias[row] + sum_k W[row][k] * xh[k][b]
// thread tile: 3 rows x 2 batch. 128 threads cover 24 rows x 32 batch.
template<int KLEN, int KP>
__device__ __forceinline__ void gate_mm(const float* __restrict__ Ws,
                                        const float* __restrict__ xb,
                                        const float* __restrict__ bias,
                                        float* __restrict__ gb, int tid)
{
    const int p = (tid & 15) * 2;    // batch pair base
    const int r = (tid >> 4) * 3;    // row triple base
    const float* w0 = Ws + r * KP;
    const float* w1 = w0 + KP;
    const float* w2 = w1 + KP;
    const float* xp = xb + p;
    float a00 = 0.f, a01 = 0.f, a10 = 0.f, a11 = 0.f, a20 = 0.f, a21 = 0.f;
    #pragma unroll 10
    for (int k = 0; k < KLEN; k += 2) {
        float2 xa = *(const float2*)(xp + k * XSTR);
        float2 xc = *(const float2*)(xp + (k + 1) * XSTR);
        float2 wa = *(const float2*)(w0 + k);
        float2 wb = *(const float2*)(w1 + k);
        float2 wc = *(const float2*)(w2 + k);
        a00 = fmaf(wa.x, xa.x, a00); a01 = fmaf(wa.x, xa.y, a01);
        a10 = fmaf(wb.x, xa.x, a10); a11 = fmaf(wb.x, xa.y, a11);
        a20 = fmaf(wc.x, xa.x, a20); a21 = fmaf(wc.x, xa.y, a21);
        a00 = fmaf(wa.y, xc.x, a00); a01 = fmaf(wa.y, xc.y, a01);
        a10 = fmaf(wb.y, xc.x, a10); a11 = fmaf(wb.y, xc.y, a11);
        a20 = fmaf(wc.y, xc.x, a20); a21 = fmaf(wc.y, xc.y, a21);
    }
    gb[(r + 0) * MB + p]     = a00 + bias[r + 0];
    gb[(r + 0) * MB + p + 1] = a01 + bias[r + 0];
    gb[(r + 1) * MB + p]     = a10 + bias[r + 1];
    gb[(r + 1) * MB + p + 1] = a11 + bias[r + 1];
    gb[(r + 2) * MB + p]     = a20 + bias[r + 2];
    gb[(r + 2) * MB + p + 1] = a21 + bias[r + 2];
}

// LSTM pointwise: update c (smem), write h to global ping-pong (+ optional y1)
__device__ __forceinline__ void pointwise(const float* __restrict__ gb,
                                          float* __restrict__ cs,
                                          float* __restrict__ hglob,
                                          float* __restrict__ yglob,
                                          int hs, int b0, int tid)
{
    for (int e = tid; e < NHU * MB; e += NTHR) {
        int u = e >> 5, b = e & 31;
        int j = hs + u;
        float gi = gb[u * MB + b];
        float gf = gb[(NHU + u) * MB + b];
        float gg = gb[(2 * NHU + u) * MB + b];
        float go = gb[(3 * NHU + u) * MB + b];
        float c = cs[e];
        c = sigm(gf) * c + sigm(gi) * tanha(gg);
        float h = sigm(go) * tanha(c);
        cs[e] = c;
        if (j < HID) {
            hglob[j * BATCH + b0 + b] = h;
            if (yglob) yglob[j * BATCH + b0 + b] = h;
        }
    }
}

__global__ void __launch_bounds__(NTHR, 1)
lstm_pers_kernel(const float* __restrict__ inp,  const float* __restrict__ h0in,
                 const float* __restrict__ c0in,
                 const float* __restrict__ Wih0, const float* __restrict__ Whh0,
                 const float* __restrict__ bih0, const float* __restrict__ bhh0,
                 const float* __restrict__ Wih1, const float* __restrict__ Whh1,
                 const float* __restrict__ bih1, const float* __restrict__ bhh1,
                 float* __restrict__ out)
{
    extern __shared__ float sm[];
    float* W0s   = sm + OFF_W0;   // [NG][K0]
    float* W1s   = sm + OFF_W1;   // [NG][K1]
    float* xh    = sm + OFF_XH;   // [500][XSTR]: rows 0..99 x_t, 100..299 h0, 300..499 h1
    float* gb    = sm + OFF_GB;   // [NG][MB]
    float* bias0 = sm + OFF_B0;
    float* bias1 = sm + OFF_B1;
    float* c0s   = sm + OFF_C0;   // [NHU][MB]
    float* c1s   = sm + OFF_C1;

    const int tid = threadIdx.x;
    const int bg  = blockIdx.x / NHG;
    const int hg  = blockIdx.x % NHG;
    const int b0  = bg * MB;
    const int hs  = hg * NHU;

    // ---- load weight slices (resident all run); invalid rows (j>=HID) zero ----
    for (int i = tid; i < NG * K0; i += NTHR) {
        int c = i / K0, k = i - c * K0;
        int gate = c / NHU, u = c - gate * NHU;
        int j = hs + u, row = gate * HID + j;
        float v = 0.f;
        if (j < HID) v = (k < INDIM) ? Wih0[row * INDIM + k] : Whh0[row * HID + (k - INDIM)];
        W0s[c * K0 + k] = v;
    }
    for (int i = tid; i < NG * K1; i += NTHR) {
        int c = i / K1, k = i - c * K1;
        int gate = c / NHU, u = c - gate * NHU;
        int j = hs + u, row = gate * HID + j;
        float v = 0.f;
        if (j < HID) v = (k < HID) ? Wih1[row * HID + k] : Whh1[row * HID + (k - HID)];
        W1s[c * K1 + k] = v;
    }
    if (tid < NG) {
        int gate = tid / NHU, u = tid - gate * NHU;
        int j = hs + u, row = gate * HID + j;
        bias0[tid] = (j < HID) ? bih0[row] + bhh0[row] : 0.f;
        bias1[tid] = (j < HID) ? bih1[row] + bhh1[row] : 0.f;
    }

    // ---- init cell state + publish initial h into ping-pong slots ----
    for (int e = tid; e < NHU * MB; e += NTHR) {
        int u = e >> 5, b = e & 31, j = hs + u;
        float cv0 = 0.f, cv1 = 0.f;
        if (j < HID) {
            cv0 = c0in[(b0 + b) * HID + j];
            cv1 = c0in[BATCH * HID + (b0 + b) * HID + j];
            g_ph0[1][j * BATCH + b0 + b] = h0in[(b0 + b) * HID + j];               // h0_{-1}
            g_ph1[0][j * BATCH + b0 + b] = h0in[BATCH * HID + (b0 + b) * HID + j]; // h1_{-1}
        }
        c0s[e] = cv0;
        c1s[e] = cv1;
    }

    unsigned bep = 0;
    group_barrier(bg, (++bep) * NHG);

    // ---- pipelined main loop: iter i does layer0(step i) and layer1(step i-1) ----
    for (int iter = 0; iter <= T_STEPS; ++iter) {
        // stage x_iter
        if (iter < T_STEPS) {
            const float* xsrc = inp + (size_t)iter * BATCH * INDIM + (size_t)b0 * INDIM;
            for (int idx = tid; idx < MB * INDIM; idx += NTHR) {
                int b = idx / INDIM, k = idx - b * INDIM;
                xh[k * XSTR + b] = __ldg(xsrc + b * INDIM + k);
            }
        }
        // stage h0_{iter-1}
        {
            const float* ph0 = g_ph0[(iter + 1) & 1];
            for (int idx = tid; idx < HID * (MB / 4); idx += NTHR) {
                int j = idx >> 3, q = idx & 7;
                float4 v = __ldcg((const float4*)(ph0 + j * BATCH + b0 + q * 4));
                *(float4*)(&xh[(INDIM + j) * XSTR + q * 4]) = v;
            }
        }
        // stage h1_{iter-2}
        if (iter >= 1) {
            const float* ph1 = g_ph1[(iter + 1) & 1];
            for (int idx = tid; idx < HID * (MB / 4); idx += NTHR) {
                int j = idx >> 3, q = idx & 7;
                float4 v = __ldcg((const float4*)(ph1 + j * BATCH + b0 + q * 4));
                *(float4*)(&xh[(INDIM + HID + j) * XSTR + q * 4]) = v;
            }
        }
        __syncthreads();

        if (iter < T_STEPS) {
            gate_mm<K0, K0>(W0s, xh, bias0, gb, tid);
            __syncthreads();
            pointwise(gb, c0s, g_ph0[iter & 1], nullptr, hs, b0, tid);
            __syncthreads();
        }
        if (iter >= 1) {
            gate_mm<K1, K1>(W1s, xh + INDIM * XSTR, bias1, gb, tid);
            __syncthreads();
            pointwise(gb, c1s, g_ph1[iter & 1],
                      g_y1 + (size_t)(iter - 1) * HID * BATCH, hs, b0, tid);
        }
        group_barrier(bg, (++bep) * NHG);
    }

    // ---- epilogue: hn, cn (own slices only; own writes, read via L2) ----
    const float* hf0 = g_ph0[(T_STEPS - 1) & 1];
    const float* hf1 = g_ph1[T_STEPS & 1];
    for (int e = tid; e < NHU * MB; e += NTHR) {
        int u = e >> 5, b = e & 31, j = hs + u;
        if (j < HID) {
            out[HN_OFF + (b0 + b) * HID + j]               = __ldcg(hf0 + j * BATCH + b0 + b);
            out[HN_OFF + BATCH * HID + (b0 + b) * HID + j] = __ldcg(hf1 + j * BATCH + b0 + b);
            out[CN_OFF + (b0 + b) * HID + j]               = c0s[e];
            out[CN_OFF + BATCH * HID + (b0 + b) * HID + j] = c1s[e];
        }
    }
}

// -------- FC head: out[t,b,c] = fcb[c] + sum_h fcW[c][h] * y1[t,h,b] --------
__global__ void __launch_bounds__(256, 1)
fc_kernel(const float* __restrict__ fcW, const float* __restrict__ fcb,
          float* __restrict__ out)
{
    extern __shared__ float s[];
    float* Ws = s;                 // [NCLS][HID]
    float* bs = s + NCLS * HID;    // [NCLS]
    int tid = threadIdx.x;
    for (int i = tid; i < NCLS * HID; i += 256) Ws[i] = fcW[i];
    if (tid < NCLS) bs[tid] = fcb[tid];
    __syncthreads();

    int t = blockIdx.x;
    const float* y = g_y1 + (size_t)t * HID * BATCH;   // [HID][BATCH]
    float* o = out + (size_t)t * BATCH * NCLS;

    int bq  = (tid & 31) * 4;      // batch base (4 batches)
    int cq0 = tid >> 5;            // class-quad start (8 per pass, 25 total)
    for (int cq = cq0; cq < 25; cq += 8) {
        int c0 = cq * 4;
        float acc[4][4];
        #pragma unroll
        for (int jc = 0; jc < 4; jc++) {
            float bv = bs[c0 + jc];
            #pragma unroll
            for (int jb = 0; jb < 4; jb++) acc[jc][jb] = bv;
        }
        for (int k = 0; k < HID; ++k) {
            float4 yv = *(const float4*)(y + k * BATCH + bq);
            #pragma unroll
            for (int jc = 0; jc < 4; jc++) {
                float w = Ws[(c0 + jc) * HID + k];
                acc[jc][0] = fmaf(w, yv.x, acc[jc][0]);
                acc[jc][1] = fmaf(w, yv.y, acc[jc][1]);
                acc[jc][2] = fmaf(w, yv.z, acc[jc][2]);
                acc[jc][3] = fmaf(w, yv.w, acc[jc][3]);
            }
        }
        #pragma unroll
        for (int jb = 0; jb < 4; jb++) {
            float4 v = make_float4(acc[0][jb], acc[1][jb], acc[2][jb], acc[3][jb]);
            *(float4*)(o + (bq + jb) * NCLS + c0) = v;
        }
    }
}

extern "C" void kernel_launch(void* const* d_in, const int* in_sizes, int n_in,
                              void* d_out, int out_size)
{
    (void)in_sizes; (void)n_in; (void)out_size;
    const float* inp  = (const float*)d_in[0];
    const float* h0   = (const float*)d_in[1];
    const float* c0   = (const float*)d_in[2];
    const float* Wih0 = (const float*)d_in[3];
    const float* Whh0 = (const float*)d_in[4];
    const float* bih0 = (const float*)d_in[5];
    const float* bhh0 = (const float*)d_in[6];
    const float* Wih1 = (const float*)d_in[7];
    const float* Whh1 = (const float*)d_in[8];
    const float* bih1 = (const float*)d_in[9];
    const float* bhh1 = (const float*)d_in[10];
    const float* fcW  = (const float*)d_in[11];
    const float* fcb  = (const float*)d_in[12];
    float* out = (float*)d_out;

    cudaFuncSetAttribute(lstm_pers_kernel,
                         cudaFuncAttributeMaxDynamicSharedMemorySize, SMEM_BYTES);
    cudaFuncSetAttribute(fc_kernel,
                         cudaFuncAttributeMaxDynamicSharedMemorySize, FC_SMEM_BYTES);

    bar_reset_kernel<<<1, 128>>>();
    lstm_pers_kernel<<<NCTA, NTHR, SMEM_BYTES>>>(inp, h0, c0,
                                                 Wih0, Whh0, bih0, bhh0,
                                                 Wih1, Whh1, bih1, bhh1, out);
    fc_kernel<<<T_STEPS, 256, FC_SMEM_BYTES>>>(fcW, fcb, out);
}